// round 8
// baseline (speedup 1.0000x reference)
#include <cuda_runtime.h>
#include <cstdint>

#define B_ 2
#define N_ 65536
#define H_ 8
#define TILES_PER_CTA 8
#define NCHUNK 64

// ---- smem layout (float offsets) ----
#define PW    260
#define SW_F  0                    // W [n 0..127][k 0..255] pitch 260 (p cols 0-63, fx 64-127)
#define SX_F  33280                // 2 x (128 tok x 36 pitch) chunk bufs ; aliased by sFxT
#define PXC   36
#define BUFB  (128 * PXC * 4)      // 18432 B per buf
#define PT    132                  // transposed fx / w pitch
#define SP_F  42496                // p [tok][d] pitch 68 ; aliased by sWgtT [s][tok] AND x buf2
#define PP    68
#define SSL_F 51200                // Wsl [s][d] pitch 68
#define SRED_F 55552               // softmax exchange: max [0..255], sum [256..511]
#define SBIAS_F 56064              // 128 floats
#define SMEM_FLOATS 56192          // 224768 B

__device__ float g_A[B_ * H_ * 64 * 64];
__device__ float g_norm[B_ * H_ * 64];

__device__ __forceinline__ uint32_t smem_u32(const void* p) {
    uint32_t a;
    asm("{ .reg .u64 t; cvta.to.shared.u64 t, %1; cvt.u32.u64 %0, t; }" : "=r"(a) : "l"(p));
    return a;
}
__device__ __forceinline__ unsigned f2tf(float x) {
    unsigned r; asm("cvt.rna.tf32.f32 %0, %1;" : "=r"(r) : "f"(x)); return r;
}
__device__ __forceinline__ float tfF(float x) { return __uint_as_float(f2tf(x)); }

__device__ __forceinline__ void mma8(float* d, unsigned a0, unsigned a1, unsigned a2,
                                     unsigned a3, unsigned b0, unsigned b1) {
    asm volatile("mma.sync.aligned.m16n8k8.row.col.f32.tf32.tf32.f32 "
                 "{%0,%1,%2,%3},{%4,%5,%6,%7},{%8,%9},{%0,%1,%2,%3};"
                 : "+f"(d[0]), "+f"(d[1]), "+f"(d[2]), "+f"(d[3])
                 : "r"(a0), "r"(a1), "r"(a2), "r"(a3), "r"(b0), "r"(b1));
}
__device__ __forceinline__ void ldsm4(uint32_t addr, unsigned& r0, unsigned& r1,
                                      unsigned& r2, unsigned& r3) {
    asm volatile("ldmatrix.sync.aligned.m8n8.x4.shared.b16 {%0,%1,%2,%3}, [%4];"
                 : "=r"(r0), "=r"(r1), "=r"(r2), "=r"(r3) : "r"(addr));
}
__device__ __forceinline__ void cpa16(uint32_t dst, const void* src) {
    asm volatile("cp.async.cg.shared.global [%0], [%1], 16;" :: "r"(dst), "l"(src));
}
#define CPA_COMMIT() asm volatile("cp.async.commit_group;" ::: "memory")
#define CPA_WAIT1()  asm volatile("cp.async.wait_group 1;" ::: "memory")
#define CPA_WAIT0()  asm volatile("cp.async.wait_group 0;" ::: "memory")

__global__ void k_zero() {
    int i = blockIdx.x * 256 + threadIdx.x;
    if (i < B_ * H_ * 64 * 64) g_A[i] = 0.0f;
    if (i < B_ * H_ * 64)      g_norm[i] = 0.0f;
}

__global__ __launch_bounds__(512, 1)
void k_fused(const float* __restrict__ x,
             const float* __restrict__ Wx,  const float* __restrict__ bx,
             const float* __restrict__ Wfx, const float* __restrict__ bfx,
             const float* __restrict__ Wsl, const float* __restrict__ bsl,
             const float* __restrict__ temp)
{
    extern __shared__ float sm[];
    float* sW    = sm + SW_F;
    float* sP    = sm + SP_F;
    float* sWgtT = sm + SP_F;      // alias (also x buf2 during main loop)
    float* sFxT  = sm + SX_F;      // alias (x bufs 0/1 during main loop)
    float* sSl   = sm + SSL_F;
    float* sRedM = sm + SRED_F;
    float* sRedS = sm + SRED_F + 256;
    float* sBias = sm + SBIAS_F;

    const uint32_t sb   = smem_u32(sm);
    const uint32_t sXu  = sb + SX_F * 4;
    const uint32_t sWu  = sb + SW_F * 4;
    const uint32_t sPu  = sb + SP_F * 4;
    const uint32_t sSlu = sb + SSL_F * 4;
    const uint32_t sWgtu = sPu;
    const uint32_t sFxu  = sXu;

    const int tid  = threadIdx.x;
    // grid = (H, NCHUNK, B): the 8 head-CTAs sharing an x-range are bid-adjacent -> L2 reuse
    const int h = blockIdx.x, b = blockIdx.z;
    const int lane = tid & 31, wid = tid >> 5;
    const int g    = lane >> 2, t = lane & 3;

    // main GEMM roles: 4 m-warps x 4 n-warps
    const int tokBase = (wid >> 2) * 32;
    const int nw      = wid & 3;
    const int colBase = nw * 32;
    // slice roles: 8 m-warps x 2 n-warps
    const int smw = wid >> 1, snw = wid & 1;
    const int tokB2 = smw * 16, sB2 = snw * 32;
    // agg roles: 4 (s) x 4 (d)
    const int sB3 = (wid >> 2) * 16, dB3 = (wid & 3) * 16;

    // ---- stage W [n][k] plain, tf32 ----
    {
        const float4* Wx4  = (const float4*)Wx;
        const float4* Wfx4 = (const float4*)Wfx;
        #pragma unroll
        for (int it = 0; it < 16; it++) {
            int f = tid + it * 512;            // 0..8191
            int k = f >> 5, q = f & 31;
            float4 v = (q < 16) ? Wx4[k * 128 + h * 16 + q]
                                : Wfx4[k * 128 + h * 16 + (q - 16)];
            int n = 4 * q;
            sW[(n + 0) * PW + k] = tfF(v.x);
            sW[(n + 1) * PW + k] = tfF(v.y);
            sW[(n + 2) * PW + k] = tfF(v.z);
            sW[(n + 3) * PW + k] = tfF(v.w);
        }
        #pragma unroll
        for (int it = 0; it < 8; it++) {
            int f = tid + it * 512;            // 0..4095
            int d = f >> 6, s = f & 63;
            sSl[s * PP + d] = tfF(Wsl[f]);
        }
        if (tid < 128)
            sBias[tid] = (tid < 64) ? bx[h * 64 + tid] : bfx[h * 64 + (tid - 64)];
    }
    __syncthreads();

    float tv = fminf(fmaxf(temp[h], 0.5f), 5.0f);
    const float invT = 1.0f / tv;
    float bS[8];
    #pragma unroll
    for (int j = 0; j < 4; j++)
        #pragma unroll
        for (int e = 0; e < 2; e++) bS[2 * j + e] = bsl[sB2 + 8 * j + 2 * t + e];

    // ldmatrix per-thread bases
    const int rA = (lane & 7) + 8 * ((lane >> 3) & 1);
    const int cA = (lane >> 4) & 1;
    const uint32_t aA0rel = (uint32_t)(tokBase + rA) * (PXC * 4) + cA * 16;
    const int rB = (lane & 7) + 8 * ((lane >> 4) & 1);
    const int cB = (lane >> 3) & 1;
    const uint32_t bB0 = sWu + (uint32_t)(colBase + rB) * (PW * 4) + cB * 16;
    const uint32_t pA0 = sPu + (uint32_t)(tokB2 + rA) * (PP * 4) + cA * 16;
    const uint32_t slB0 = sSlu + (uint32_t)(sB2 + rB) * (PP * 4) + cB * 16;
    const uint32_t wA0 = sWgtu + (uint32_t)(sB3 + rA) * (PT * 4) + cA * 16;
    const uint32_t fB0 = sFxu + (uint32_t)(dB3 + rB) * (PT * 4) + cB * 16;

    float aggAcc[2][4];
    #pragma unroll
    for (int j = 0; j < 2; j++)
        #pragma unroll
        for (int e = 0; e < 4; e++) aggAcc[j][e] = 0.0f;
    float na[8];
    #pragma unroll
    for (int i = 0; i < 8; i++) na[i] = 0.0f;

    const float4* xg4 = (const float4*)x + (size_t)b * (size_t)N_ * 64;
    const int cTok = tid >> 2, cQ = 2 * (tid & 3);
    const uint32_t dstRel = (uint32_t)cTok * (PXC * 4) + cQ * 16;

    for (int tnum = 0; tnum < TILES_PER_CTA; tnum++) {
        const int n0 = (blockIdx.y * TILES_PER_CTA + tnum) * 128;
        __syncthreads();   // epilogue reads of aliased regions done

        float acc[2][4][4];
        #pragma unroll
        for (int i = 0; i < 2; i++)
            #pragma unroll
            for (int j = 0; j < 4; j++)
                #pragma unroll
                for (int e = 0; e < 4; e++) acc[i][j][e] = 0.0f;

        const float4* srcRow = xg4 + (size_t)(n0 + cTok) * 64 + cQ;

        // prologue: chunks 0,1 -> bufs 0,1
        #pragma unroll
        for (int c = 0; c < 2; c++) {
            uint32_t dst = sXu + c * BUFB + dstRel;
            cpa16(dst, srcRow + c * 8); cpa16(dst + 16, srcRow + c * 8 + 1);
            CPA_COMMIT();
        }

        // 3-buffer rotating pipeline: 1 barrier per chunk, loads issued before compute
        uint32_t bufCur = sXu, bufNxt = sXu + BUFB, bufFar = sPu;
        for (int c = 0; c < 8; c++) {
            if (c < 7) CPA_WAIT1(); else CPA_WAIT0();
            __syncthreads();
            if (c < 6) {
                uint32_t dst = bufFar + dstRel;
                const float4* src = srcRow + (c + 2) * 8;
                cpa16(dst, src); cpa16(dst + 16, src + 1);
                CPA_COMMIT();
            }

            const uint32_t aB = bufCur + aA0rel;
            const uint32_t kB = bB0 + (uint32_t)c * 128;
            #pragma unroll
            for (int ksl = 0; ksl < 4; ksl++) {
                unsigned a0[4], a1[4], p0, p1, p2, p3;
                ldsm4(aB + ksl * 32, a0[0], a0[1], a0[2], a0[3]);
                ldsm4(aB + 16 * (PXC * 4) + ksl * 32, a1[0], a1[1], a1[2], a1[3]);
                ldsm4(kB + ksl * 32, p0, p1, p2, p3);
                mma8(acc[0][0], a0[0], a0[1], a0[2], a0[3], p0, p1);
                mma8(acc[0][1], a0[0], a0[1], a0[2], a0[3], p2, p3);
                mma8(acc[1][0], a1[0], a1[1], a1[2], a1[3], p0, p1);
                mma8(acc[1][1], a1[0], a1[1], a1[2], a1[3], p2, p3);
                ldsm4(kB + 16 * (PW * 4) + ksl * 32, p0, p1, p2, p3);
                mma8(acc[0][2], a0[0], a0[1], a0[2], a0[3], p0, p1);
                mma8(acc[0][3], a0[0], a0[1], a0[2], a0[3], p2, p3);
                mma8(acc[1][2], a1[0], a1[1], a1[2], a1[3], p0, p1);
                mma8(acc[1][3], a1[0], a1[1], a1[2], a1[3], p2, p3);
            }
            uint32_t tmp = bufCur; bufCur = bufNxt; bufNxt = bufFar; bufFar = tmp;
        }
        __syncthreads();   // all computes done before aliased-region writes

        // ---- p / fx stores ----
        if (nw < 2) {
            #pragma unroll
            for (int i = 0; i < 2; i++)
                #pragma unroll
                for (int j = 0; j < 4; j++) {
                    int row = tokBase + 16 * i + g;
                    int col = colBase + 8 * j + 2 * t;
                    *(float2*)&sP[row * PP + col] = make_float2(
                        tfF(acc[i][j][0] + sBias[col]), tfF(acc[i][j][1] + sBias[col + 1]));
                    *(float2*)&sP[(row + 8) * PP + col] = make_float2(
                        tfF(acc[i][j][2] + sBias[col]), tfF(acc[i][j][3] + sBias[col + 1]));
                }
        } else {
            #pragma unroll
            for (int i = 0; i < 2; i++)
                #pragma unroll
                for (int j = 0; j < 4; j++) {
                    int row = tokBase + 16 * i + g;
                    #pragma unroll
                    for (int e = 0; e < 2; e++) {
                        int d = (colBase - 64) + 8 * j + 2 * t + e;
                        sFxT[d * PT + row]     = tfF(acc[i][j][e]     + sBias[64 + d]);
                        sFxT[d * PT + row + 8] = tfF(acc[i][j][2 + e] + sBias[64 + d]);
                    }
                }
        }
        __syncthreads();

        // ---- slice GEMM: warp = 16 tokens x 32 s ----
        float accS[4][4];
        #pragma unroll
        for (int j = 0; j < 4; j++)
            #pragma unroll
            for (int e = 0; e < 4; e++) accS[j][e] = 0.0f;
        #pragma unroll
        for (int ks = 0; ks < 8; ks++) {
            unsigned a0, a1, a2, a3, p0, p1, p2, p3;
            ldsm4(pA0 + ks * 32, a0, a1, a2, a3);
            ldsm4(slB0 + ks * 32, p0, p1, p2, p3);
            mma8(accS[0], a0, a1, a2, a3, p0, p1);
            mma8(accS[1], a0, a1, a2, a3, p2, p3);
            ldsm4(slB0 + 16 * (PP * 4) + ks * 32, p0, p1, p2, p3);
            mma8(accS[2], a0, a1, a2, a3, p0, p1);
            mma8(accS[3], a0, a1, a2, a3, p2, p3);
        }

        // ---- softmax: 64 s split across snw pair, smem exchange ----
        float w0[8], w1[8];
        #pragma unroll
        for (int j = 0; j < 4; j++)
            #pragma unroll
            for (int e = 0; e < 2; e++) {
                w0[2 * j + e] = (accS[j][e]     + bS[2 * j + e]) * invT;
                w1[2 * j + e] = (accS[j][2 + e] + bS[2 * j + e]) * invT;
            }
        float m0 = w0[0], m1 = w1[0];
        #pragma unroll
        for (int i = 1; i < 8; i++) { m0 = fmaxf(m0, w0[i]); m1 = fmaxf(m1, w1[i]); }
        m0 = fmaxf(m0, __shfl_xor_sync(0xffffffffu, m0, 1));
        m0 = fmaxf(m0, __shfl_xor_sync(0xffffffffu, m0, 2));
        m1 = fmaxf(m1, __shfl_xor_sync(0xffffffffu, m1, 1));
        m1 = fmaxf(m1, __shfl_xor_sync(0xffffffffu, m1, 2));
        const int row0 = tokB2 + g, row1 = row0 + 8;
        if (t == 0) { sRedM[snw * 128 + row0] = m0; sRedM[snw * 128 + row1] = m1; }
        __syncthreads();
        float M0 = fmaxf(m0, sRedM[(1 ^ snw) * 128 + row0]);
        float M1 = fmaxf(m1, sRedM[(1 ^ snw) * 128 + row1]);
        float s0 = 0.0f, s1 = 0.0f;
        #pragma unroll
        for (int i = 0; i < 8; i++) {
            w0[i] = __expf(w0[i] - M0); s0 += w0[i];
            w1[i] = __expf(w1[i] - M1); s1 += w1[i];
        }
        s0 += __shfl_xor_sync(0xffffffffu, s0, 1);
        s0 += __shfl_xor_sync(0xffffffffu, s0, 2);
        s1 += __shfl_xor_sync(0xffffffffu, s1, 1);
        s1 += __shfl_xor_sync(0xffffffffu, s1, 2);
        if (t == 0) { sRedS[snw * 128 + row0] = s0; sRedS[snw * 128 + row1] = s1; }
        __syncthreads();
        float r0inv = __frcp_rn(s0 + sRedS[(1 ^ snw) * 128 + row0]);
        float r1inv = __frcp_rn(s1 + sRedS[(1 ^ snw) * 128 + row1]);

        // ---- w stores (transposed [s][tok]) + norm accumulation ----
        #pragma unroll
        for (int j = 0; j < 4; j++)
            #pragma unroll
            for (int e = 0; e < 2; e++) {
                int s = sB2 + 8 * j + 2 * t + e;
                float v0 = tfF(w0[2 * j + e] * r0inv);
                float v1 = tfF(w1[2 * j + e] * r1inv);
                sWgtT[s * PT + row0] = v0;
                sWgtT[s * PT + row1] = v1;
                na[2 * j + e] += v0 + v1;
            }
        __syncthreads();

        // ---- aggregation: A[s,d] += w^T @ fx, K=128 tokens ----
        #pragma unroll
        for (int ks = 0; ks < 16; ks++) {
            unsigned a0, a1, a2, a3, p0, p1, p2, p3;
            ldsm4(wA0 + ks * 32, a0, a1, a2, a3);
            ldsm4(fB0 + ks * 32, p0, p1, p2, p3);
            mma8(aggAcc[0], a0, a1, a2, a3, p0, p1);
            mma8(aggAcc[1], a0, a1, a2, a3, p2, p3);
        }
    }

    // ---- flush ----
    float* gA = g_A + (size_t)((b * H_ + h) * 64) * 64;
    #pragma unroll
    for (int j = 0; j < 2; j++) {
        int d0 = dB3 + 8 * j + 2 * t;
        atomicAdd(&gA[(sB3 + g) * 64 + d0],         aggAcc[j][0]);
        atomicAdd(&gA[(sB3 + g) * 64 + d0 + 1],     aggAcc[j][1]);
        atomicAdd(&gA[(sB3 + g + 8) * 64 + d0],     aggAcc[j][2]);
        atomicAdd(&gA[(sB3 + g + 8) * 64 + d0 + 1], aggAcc[j][3]);
    }
    #pragma unroll
    for (int i = 0; i < 8; i++) {
        float v = na[i];
        v += __shfl_xor_sync(0xffffffffu, v, 4);
        v += __shfl_xor_sync(0xffffffffu, v, 8);
        v += __shfl_xor_sync(0xffffffffu, v, 16);
        if (lane < 4)
            atomicAdd(&g_norm[(b * H_ + h) * 64 + sB2 + 8 * (i >> 1) + 2 * t + (i & 1)], v);
    }
}

__global__ void k_final(float* __restrict__ out) {
    int i = blockIdx.x * 256 + threadIdx.x;
    out[i] = g_A[i] / (g_norm[i >> 6] + 0.01f);
}

extern "C" void kernel_launch(void* const* d_in, const int* in_sizes, int n_in,
                              void* d_out, int out_size) {
    const float* x    = (const float*)d_in[0];
    const float* Wx   = (const float*)d_in[1];
    const float* bx   = (const float*)d_in[2];
    const float* Wfx  = (const float*)d_in[3];
    const float* bfx  = (const float*)d_in[4];
    const float* Wsl  = (const float*)d_in[5];
    const float* bsl  = (const float*)d_in[6];
    const float* temp = (const float*)d_in[7];
    float* out = (float*)d_out;

    const int smem_bytes = SMEM_FLOATS * 4;   // 224768 B
    cudaFuncSetAttribute(k_fused, cudaFuncAttributeMaxDynamicSharedMemorySize, smem_bytes);

    k_zero<<<256, 256>>>();
    dim3 grid(H_, NCHUNK, B_);
    k_fused<<<grid, 512, smem_bytes>>>(x, Wx, bx, Wfx, bfx, Wsl, bsl, temp);
    k_final<<<256, 256>>>(out);
}

// round 9
// speedup vs baseline: 1.9257x; 1.9257x over previous
#include <cuda_runtime.h>
#include <cuda_fp16.h>
#include <cstdint>

#define B_ 2
#define N_ 65536
#define H_ 8
#define TILES_PER_CTA 8
#define NCHUNK 64

// ---- smem layout (byte offsets); every pitch = 16 mod 128 bytes ----
#define PWB   528                   // W pitch: 264 halves
#define SW_B  0                     // W [n 0..127][k 0..255] fp16 : 128*528 = 67584
#define PXB   144                   // x chunk pitch: 72 halves (64 k + pad)
#define SX_B  67584                 // x chunk [tok 0..127][k 0..63] fp16 : 18432 ; alias sFxT [d][tok] pitch 272
#define PPB   144                   // p pitch: 72 halves
#define SP_B  86016                 // p [tok][d] fp16 : 18432 ; alias sWgtT [s][tok] pitch 272
#define PTB   272                   // transposed fx / w pitch: 136 halves
#define SSL_B 104448                // Wsl [s 0..63][d 0..63] fp16 pitch 144 : 9216
#define SRED_B 113664               // softmax exchange floats: max 256, sum 256 -> 2048 B
#define SBIAS_B 115712              // 128 floats -> 512 B
#define SMEM_BYTES 116224

__device__ float g_A[B_ * H_ * 64 * 64];
__device__ float g_norm[B_ * H_ * 64];

__device__ __forceinline__ uint32_t smem_u32(const void* p) {
    uint32_t a;
    asm("{ .reg .u64 t; cvta.to.shared.u64 t, %1; cvt.u32.u64 %0, t; }" : "=r"(a) : "l"(p));
    return a;
}
__device__ __forceinline__ uint32_t f22h2(float a, float b) {
    __half2 h = __floats2half2_rn(a, b);
    return *reinterpret_cast<uint32_t*>(&h);
}

__device__ __forceinline__ void mma16(float* d, const unsigned* a, unsigned b0, unsigned b1) {
    asm volatile("mma.sync.aligned.m16n8k16.row.col.f32.f16.f16.f32 "
                 "{%0,%1,%2,%3},{%4,%5,%6,%7},{%8,%9},{%0,%1,%2,%3};"
                 : "+f"(d[0]), "+f"(d[1]), "+f"(d[2]), "+f"(d[3])
                 : "r"(a[0]), "r"(a[1]), "r"(a[2]), "r"(a[3]), "r"(b0), "r"(b1));
}
__device__ __forceinline__ void ldsm4(uint32_t addr, unsigned* r) {
    asm volatile("ldmatrix.sync.aligned.m8n8.x4.shared.b16 {%0,%1,%2,%3}, [%4];"
                 : "=r"(r[0]), "=r"(r[1]), "=r"(r[2]), "=r"(r[3]) : "r"(addr));
}

__global__ void k_zero() {
    int i = blockIdx.x * 256 + threadIdx.x;
    if (i < B_ * H_ * 64 * 64) g_A[i] = 0.0f;
    if (i < B_ * H_ * 64)      g_norm[i] = 0.0f;
}

__global__ __launch_bounds__(512, 1)
void k_fused(const float* __restrict__ x,
             const float* __restrict__ Wx,  const float* __restrict__ bx,
             const float* __restrict__ Wfx, const float* __restrict__ bfx,
             const float* __restrict__ Wsl, const float* __restrict__ bsl,
             const float* __restrict__ temp)
{
    extern __shared__ char smb[];
    __half* sWh  = (__half*)(smb + SW_B);
    __half* sSlh = (__half*)(smb + SSL_B);
    float*  sRedM = (float*)(smb + SRED_B);
    float*  sRedS = (float*)(smb + SRED_B + 1024);
    float*  sBias = (float*)(smb + SBIAS_B);

    const uint32_t sb   = smem_u32(smb);
    const uint32_t sXu  = sb + SX_B;
    const uint32_t sWu  = sb + SW_B;
    const uint32_t sPu  = sb + SP_B;
    const uint32_t sSlu = sb + SSL_B;

    const int tid  = threadIdx.x;
    const int b    = blockIdx.z, h = blockIdx.y;
    const int lane = tid & 31, wid = tid >> 5;
    const int g    = lane >> 2, t = lane & 3;

    // main GEMM roles: 4 m-warps x 4 n-warps
    const int tokBase = (wid >> 2) * 32;
    const int nw      = wid & 3;
    const int colBase = nw * 32;
    // slice roles: 8 m-warps x 2 n-warps
    const int smw = wid >> 1, snw = wid & 1;
    const int tokB2 = smw * 16, sB2 = snw * 32;
    // agg roles: 4 (s) x 4 (d)
    const int sB3 = (wid >> 2) * 16, dB3 = (wid & 3) * 16;

    // ---- stage W [n][k] fp16 ----
    {
        const float4* Wx4  = (const float4*)Wx;
        const float4* Wfx4 = (const float4*)Wfx;
        #pragma unroll
        for (int it = 0; it < 16; it++) {
            int f = tid + it * 512;            // 0..8191
            int k = f >> 5, q = f & 31;
            float4 v = (q < 16) ? Wx4[k * 128 + h * 16 + q]
                                : Wfx4[k * 128 + h * 16 + (q - 16)];
            int n = 4 * q;
            sWh[(n + 0) * 264 + k] = __float2half_rn(v.x);
            sWh[(n + 1) * 264 + k] = __float2half_rn(v.y);
            sWh[(n + 2) * 264 + k] = __float2half_rn(v.z);
            sWh[(n + 3) * 264 + k] = __float2half_rn(v.w);
        }
        #pragma unroll
        for (int it = 0; it < 8; it++) {
            int f = tid + it * 512;            // 0..4095
            int d = f >> 6, s = f & 63;
            sSlh[s * 72 + d] = __float2half_rn(Wsl[f]);
        }
        if (tid < 128)
            sBias[tid] = (tid < 64) ? bx[h * 64 + tid] : bfx[h * 64 + (tid - 64)];
    }
    __syncthreads();

    float tv = fminf(fmaxf(temp[h], 0.5f), 5.0f);
    const float invT = 1.0f / tv;
    float bS[8];
    #pragma unroll
    for (int j = 0; j < 4; j++)
        #pragma unroll
        for (int e = 0; e < 2; e++) bS[2 * j + e] = bsl[sB2 + 8 * j + 2 * t + e];

    // ldmatrix bases: canonical (lane&15)*pitch + (lane>>4)*16
    const int lr = lane & 15, lc = lane >> 4;
    const uint32_t aA0  = sXu + (uint32_t)(tokBase + lr) * PXB + lc * 16;
    const uint32_t bB0  = sWu + (uint32_t)(colBase + lr) * PWB + lc * 16;
    const uint32_t pA0  = sPu + (uint32_t)(tokB2 + lr) * PPB + lc * 16;
    const uint32_t slB0 = sSlu + (uint32_t)(sB2 + lr) * 144 + lc * 16;
    const uint32_t wA0  = sPu + (uint32_t)(sB3 + lr) * PTB + lc * 16;
    const uint32_t fB0  = sXu + (uint32_t)(dB3 + lr) * PTB + lc * 16;

    float aggAcc[2][4];
    #pragma unroll
    for (int j = 0; j < 2; j++)
        #pragma unroll
        for (int e = 0; e < 4; e++) aggAcc[j][e] = 0.0f;
    float na[8];
    #pragma unroll
    for (int i = 0; i < 8; i++) na[i] = 0.0f;

    const float4* xg4 = (const float4*)x + (size_t)b * (size_t)N_ * 64;
    const int cTok = tid >> 2, cQ = tid & 3;            // thread: 16 floats of one token
    const uint32_t stsAddr = sXu + (uint32_t)cTok * PXB + cQ * 32;

    // prefetch tile 0, chunk 0 (64 k = 16 float4 per token; this thread: 4)
    float4 xr[4];
    {
        const float4* src = xg4 + (size_t)((blockIdx.x * TILES_PER_CTA) * 128 + cTok) * 64 + cQ * 4;
        #pragma unroll
        for (int i = 0; i < 4; i++) xr[i] = src[i];
    }

    for (int tnum = 0; tnum < TILES_PER_CTA; tnum++) {
        const int n0 = (blockIdx.x * TILES_PER_CTA + tnum) * 128;
        __syncthreads();   // epilogue reads of aliased regions done

        float acc[2][4][4];
        #pragma unroll
        for (int i = 0; i < 2; i++)
            #pragma unroll
            for (int j = 0; j < 4; j++)
                #pragma unroll
                for (int e = 0; e < 4; e++) acc[i][j][e] = 0.0f;

        const float4* srcRow = xg4 + (size_t)(n0 + cTok) * 64 + cQ * 4;

        for (int c = 0; c < 4; c++) {
            // stage chunk c from regs (fp32 -> fp16)
            {
                uint4 u0, u1;
                u0.x = f22h2(xr[0].x, xr[0].y); u0.y = f22h2(xr[0].z, xr[0].w);
                u0.z = f22h2(xr[1].x, xr[1].y); u0.w = f22h2(xr[1].z, xr[1].w);
                u1.x = f22h2(xr[2].x, xr[2].y); u1.y = f22h2(xr[2].z, xr[2].w);
                u1.z = f22h2(xr[3].x, xr[3].y); u1.w = f22h2(xr[3].z, xr[3].w);
                *(uint4*)(smb + (stsAddr - sb))        = u0;
                *(uint4*)(smb + (stsAddr - sb) + 16)   = u1;
            }
            // prefetch chunk c+1
            if (c < 3) {
                const float4* src = srcRow + (c + 1) * 16;
                #pragma unroll
                for (int i = 0; i < 4; i++) xr[i] = src[i];
            }
            __syncthreads();

            const uint32_t kB = bB0 + (uint32_t)c * 128;   // 64 k * 2B per chunk
            #pragma unroll
            for (int ks = 0; ks < 4; ks++) {
                unsigned a0[4], a1[4], p0[4], p1[4];
                ldsm4(aA0 + ks * 32, a0);
                ldsm4(aA0 + 16 * PXB + ks * 32, a1);
                ldsm4(kB + ks * 32, p0);
                ldsm4(kB + 16 * PWB + ks * 32, p1);
                mma16(acc[0][0], a0, p0[0], p0[2]);
                mma16(acc[0][1], a0, p0[1], p0[3]);
                mma16(acc[0][2], a0, p1[0], p1[2]);
                mma16(acc[0][3], a0, p1[1], p1[3]);
                mma16(acc[1][0], a1, p0[0], p0[2]);
                mma16(acc[1][1], a1, p0[1], p0[3]);
                mma16(acc[1][2], a1, p1[0], p1[2]);
                mma16(acc[1][3], a1, p1[1], p1[3]);
            }
            __syncthreads();
        }

        // prefetch next tile's chunk 0 under the epilogue
        if (tnum + 1 < TILES_PER_CTA) {
            const float4* src = xg4 + (size_t)(n0 + 128 + cTok) * 64 + cQ * 4;
            #pragma unroll
            for (int i = 0; i < 4; i++) xr[i] = src[i];
        }

        // ---- p / fx stores ----
        if (nw < 2) {
            #pragma unroll
            for (int i = 0; i < 2; i++)
                #pragma unroll
                for (int j = 0; j < 4; j++) {
                    int row = tokBase + 16 * i + g;
                    int col = colBase + 8 * j + 2 * t;
                    float b0f = sBias[col], b1f = sBias[col + 1];
                    *(uint32_t*)(smb + SP_B + row * PPB + col * 2) =
                        f22h2(acc[i][j][0] + b0f, acc[i][j][1] + b1f);
                    *(uint32_t*)(smb + SP_B + (row + 8) * PPB + col * 2) =
                        f22h2(acc[i][j][2] + b0f, acc[i][j][3] + b1f);
                }
        } else {
            #pragma unroll
            for (int i = 0; i < 2; i++)
                #pragma unroll
                for (int j = 0; j < 4; j++) {
                    int row = tokBase + 16 * i + g;
                    #pragma unroll
                    for (int e = 0; e < 2; e++) {
                        int d = (colBase - 64) + 8 * j + 2 * t + e;
                        float bf = sBias[64 + d];
                        *(__half*)(smb + SX_B + d * PTB + row * 2) =
                            __float2half_rn(acc[i][j][e] + bf);
                        *(__half*)(smb + SX_B + d * PTB + (row + 8) * 2) =
                            __float2half_rn(acc[i][j][2 + e] + bf);
                    }
                }
        }
        __syncthreads();

        // ---- slice GEMM: warp = 16 tokens x 32 s, K = 64 (d) ----
        float accS[4][4];
        #pragma unroll
        for (int j = 0; j < 4; j++)
            #pragma unroll
            for (int e = 0; e < 4; e++) accS[j][e] = 0.0f;
        #pragma unroll
        for (int ks = 0; ks < 4; ks++) {
            unsigned a[4], p0[4], p1[4];
            ldsm4(pA0 + ks * 32, a);
            ldsm4(slB0 + ks * 32, p0);
            ldsm4(slB0 + 16 * 144 + ks * 32, p1);
            mma16(accS[0], a, p0[0], p0[2]);
            mma16(accS[1], a, p0[1], p0[3]);
            mma16(accS[2], a, p1[0], p1[2]);
            mma16(accS[3], a, p1[1], p1[3]);
        }

        // ---- softmax: 64 s split across snw pair, smem exchange ----
        float w0[8], w1[8];
        #pragma unroll
        for (int j = 0; j < 4; j++)
            #pragma unroll
            for (int e = 0; e < 2; e++) {
                w0[2 * j + e] = (accS[j][e]     + bS[2 * j + e]) * invT;
                w1[2 * j + e] = (accS[j][2 + e] + bS[2 * j + e]) * invT;
            }
        float m0 = w0[0], m1 = w1[0];
        #pragma unroll
        for (int i = 1; i < 8; i++) { m0 = fmaxf(m0, w0[i]); m1 = fmaxf(m1, w1[i]); }
        m0 = fmaxf(m0, __shfl_xor_sync(0xffffffffu, m0, 1));
        m0 = fmaxf(m0, __shfl_xor_sync(0xffffffffu, m0, 2));
        m1 = fmaxf(m1, __shfl_xor_sync(0xffffffffu, m1, 1));
        m1 = fmaxf(m1, __shfl_xor_sync(0xffffffffu, m1, 2));
        const int row0 = tokB2 + g, row1 = row0 + 8;
        if (t == 0) { sRedM[snw * 128 + row0] = m0; sRedM[snw * 128 + row1] = m1; }
        __syncthreads();
        float M0 = fmaxf(m0, sRedM[(1 ^ snw) * 128 + row0]);
        float M1 = fmaxf(m1, sRedM[(1 ^ snw) * 128 + row1]);
        float s0 = 0.0f, s1 = 0.0f;
        #pragma unroll
        for (int i = 0; i < 8; i++) {
            w0[i] = __expf(w0[i] - M0); s0 += w0[i];
            w1[i] = __expf(w1[i] - M1); s1 += w1[i];
        }
        s0 += __shfl_xor_sync(0xffffffffu, s0, 1);
        s0 += __shfl_xor_sync(0xffffffffu, s0, 2);
        s1 += __shfl_xor_sync(0xffffffffu, s1, 1);
        s1 += __shfl_xor_sync(0xffffffffu, s1, 2);
        if (t == 0) { sRedS[snw * 128 + row0] = s0; sRedS[snw * 128 + row1] = s1; }
        __syncthreads();
        float r0inv = __frcp_rn(s0 + sRedS[(1 ^ snw) * 128 + row0]);
        float r1inv = __frcp_rn(s1 + sRedS[(1 ^ snw) * 128 + row1]);

        // ---- w stores (fp16, transposed [s][tok]) + norm from same rounded values ----
        #pragma unroll
        for (int j = 0; j < 4; j++)
            #pragma unroll
            for (int e = 0; e < 2; e++) {
                int s = sB2 + 8 * j + 2 * t + e;
                __half v0 = __float2half_rn(w0[2 * j + e] * r0inv);
                __half v1 = __float2half_rn(w1[2 * j + e] * r1inv);
                *(__half*)(smb + SP_B + s * PTB + row0 * 2) = v0;
                *(__half*)(smb + SP_B + s * PTB + row1 * 2) = v1;
                na[2 * j + e] += __half2float(v0) + __half2float(v1);
            }
        __syncthreads();

        // ---- aggregation: A[s,d] += w^T @ fx, K = 128 tokens ----
        #pragma unroll
        for (int ks = 0; ks < 8; ks++) {
            unsigned a[4], bb[4];
            ldsm4(wA0 + ks * 32, a);
            ldsm4(fB0 + ks * 32, bb);
            mma16(aggAcc[0], a, bb[0], bb[2]);
            mma16(aggAcc[1], a, bb[1], bb[3]);
        }
    }

    // ---- flush ----
    float* gA = g_A + (size_t)((b * H_ + h) * 64) * 64;
    #pragma unroll
    for (int j = 0; j < 2; j++) {
        int d0 = dB3 + 8 * j + 2 * t;
        atomicAdd(&gA[(sB3 + g) * 64 + d0],         aggAcc[j][0]);
        atomicAdd(&gA[(sB3 + g) * 64 + d0 + 1],     aggAcc[j][1]);
        atomicAdd(&gA[(sB3 + g + 8) * 64 + d0],     aggAcc[j][2]);
        atomicAdd(&gA[(sB3 + g + 8) * 64 + d0 + 1], aggAcc[j][3]);
    }
    #pragma unroll
    for (int i = 0; i < 8; i++) {
        float v = na[i];
        v += __shfl_xor_sync(0xffffffffu, v, 4);
        v += __shfl_xor_sync(0xffffffffu, v, 8);
        v += __shfl_xor_sync(0xffffffffu, v, 16);
        if (lane < 4)
            atomicAdd(&g_norm[(b * H_ + h) * 64 + sB2 + 8 * (i >> 1) + 2 * t + (i & 1)], v);
    }
}

__global__ void k_final(float* __restrict__ out) {
    int i = blockIdx.x * 256 + threadIdx.x;
    out[i] = g_A[i] / (g_norm[i >> 6] + 0.01f);
}

extern "C" void kernel_launch(void* const* d_in, const int* in_sizes, int n_in,
                              void* d_out, int out_size) {
    const float* x    = (const float*)d_in[0];
    const float* Wx   = (const float*)d_in[1];
    const float* bx   = (const float*)d_in[2];
    const float* Wfx  = (const float*)d_in[3];
    const float* bfx  = (const float*)d_in[4];
    const float* Wsl  = (const float*)d_in[5];
    const float* bsl  = (const float*)d_in[6];
    const float* temp = (const float*)d_in[7];
    float* out = (float*)d_out;

    cudaFuncSetAttribute(k_fused, cudaFuncAttributeMaxDynamicSharedMemorySize, SMEM_BYTES);

    k_zero<<<256, 256>>>();
    dim3 grid(NCHUNK, H_, B_);
    k_fused<<<grid, 512, SMEM_BYTES>>>(x, Wx, bx, Wfx, bfx, Wsl, bsl, temp);
    k_final<<<256, 256>>>(out);
}